// round 1
// baseline (speedup 1.0000x reference)
#include <cuda_runtime.h>
#include <cstdint>

#define T_STEPS 512
#define BATCH   64
#define IN_DIM  512
#define HID     1024
#define KTOT    1536            // IN_DIM + HID
#define NCTA    128             // CTAs per step kernel
#define COLS    32              // z-columns per CTA = 4 gates x 8 hid cols
#define HPC     8               // hid columns per CTA
#define NKSTEP  (KTOT / 8)      // 192 k-steps of 8
#define CTA_W_F2 (NKSTEP * COLS * 4)   // 24576 float2 per CTA

// ---- scratch (static device memory; no allocations) ----
__device__ float2 g_Wp[(size_t)NCTA * CTA_W_F2];  // ~25 MB packed tf32 weights
__device__ float  g_bp[NCTA * COLS];              // packed bias
__device__ float  g_c[BATCH * HID];               // cell state

// tf32 round-to-nearest (keeps error unbiased; raw truncation injects ~1e-3 bias)
__device__ __forceinline__ float tf32r(float x) {
    unsigned r;
    asm("cvt.rna.tf32.f32 %0, %1;" : "=r"(r) : "f"(x));
    return __uint_as_float(r);
}

__device__ __forceinline__ void mma_tf32(float* c, float a0, float a1, float a2, float a3,
                                         float b0, float b1) {
    asm volatile(
        "mma.sync.aligned.m16n8k8.row.col.f32.tf32.tf32.f32 "
        "{%0,%1,%2,%3},{%4,%5,%6,%7},{%8,%9},{%0,%1,%2,%3};"
        : "+f"(c[0]), "+f"(c[1]), "+f"(c[2]), "+f"(c[3])
        : "r"(__float_as_uint(a0)), "r"(__float_as_uint(a1)),
          "r"(__float_as_uint(a2)), "r"(__float_as_uint(a3)),
          "r"(__float_as_uint(b0)), "r"(__float_as_uint(b1)));
}

// ---------------------------------------------------------------------------
// Pack weights into per-CTA, per-kstep mma-B-fragment order (tf32-rounded).
// float2 slot (cta, gk, ncol, ktid) = { W[gk*8+ktid][col], W[gk*8+ktid+4][col] }
// where col = cta*8 + (ncol&7) in gate (ncol>>3). Also packs bias.
// ---------------------------------------------------------------------------
__global__ void prep_kernel(const float* __restrict__ Wf, const float* __restrict__ bf,
                            const float* __restrict__ Wi, const float* __restrict__ bi,
                            const float* __restrict__ Wg, const float* __restrict__ bg,
                            const float* __restrict__ Wo, const float* __restrict__ bo) {
    int idx = blockIdx.x * blockDim.x + threadIdx.x;

    if (idx < NCTA * COLS) {  // bias packing
        int cta = idx / COLS, ncol = idx % COLS;
        int gate = ncol >> 3, cc = ncol & 7;
        const float* bsrc = gate == 0 ? bf : gate == 1 ? bi : gate == 2 ? bg : bo;
        g_bp[idx] = bsrc[cta * HPC + cc];
    }

    if (idx >= NCTA * CTA_W_F2) return;
    int cta  = idx / CTA_W_F2;
    int rem  = idx % CTA_W_F2;
    int gk   = rem >> 7;     // / 128
    int r2   = rem & 127;
    int ncol = r2 >> 2;
    int ktid = r2 & 3;
    int gate = ncol >> 3, cc = ncol & 7;
    int col  = cta * HPC + cc;
    int k0   = gk * 8;
    const float* Wsrc = gate == 0 ? Wf : gate == 1 ? Wi : gate == 2 ? Wg : Wo;
    float v0 = Wsrc[(size_t)(k0 + ktid) * HID + col];
    float v1 = Wsrc[(size_t)(k0 + ktid + 4) * HID + col];
    g_Wp[idx] = make_float2(tf32r(v0), tf32r(v1));
}

// ---------------------------------------------------------------------------
// One LSTM timestep. Grid = 128 CTAs x 256 threads. CTA `cta` owns hid columns
// [cta*8, cta*8+8) across all 4 gates (32 z-cols). Computes
// z[64,32] = [x_t, h_{t-1}] @ Wslice via tf32 mma, then gates + c/h update.
// ---------------------------------------------------------------------------
__global__ __launch_bounds__(256) void lstm_step_kernel(const float* __restrict__ x_all,
                                                        float* out, int t) {
    __shared__ __align__(16) float a_s[2][64 * 68];  // A chunk, stride 68 (conflict-free frag loads)
    __shared__ float z_s[64 * 33];
    __shared__ float bias_s[COLS];

    int tid  = threadIdx.x;
    int lane = tid & 31;
    int w    = tid >> 5;          // warp 0..7
    int gid  = lane >> 2;         // mma group id
    int ktid = lane & 3;          // mma thread-in-group
    int cta  = blockIdx.x;

    if (tid < COLS) bias_s[tid] = g_bp[cta * COLS + tid];

    const int nchunks = (t == 0) ? (IN_DIM / 64) : (KTOT / 64);  // h0 == 0 -> skip h part
    const float* hprev = out + (size_t)(t - 1) * BATCH * HID;
    const float* xrow  = x_all + (size_t)t * BATCH * IN_DIM;

    // A-tile cooperative load mapping: thread -> (row, quad-group)
    int ar = tid >> 2;   // row 0..63
    int aq = tid & 3;

    float acc0[4] = {0.f, 0.f, 0.f, 0.f};
    float acc1[4] = {0.f, 0.f, 0.f, 0.f};

    const float2* wp = g_Wp + (size_t)cta * CTA_W_F2;
    int mb    = (w & 3) * 16;     // m16 tile base row
    int nbase = (w >> 2) * 16;    // this warp's 16-col group (2 n8 tiles)

    // prefetch chunk 0 (always x region)
    float4 pre[4];
#pragma unroll
    for (int j = 0; j < 4; ++j) {
        int kg = (aq + 4 * j) * 4;
        pre[j] = *(const float4*)(xrow + (size_t)ar * IN_DIM + kg);
    }

    for (int c = 0; c < nchunks; ++c) {
        int buf = c & 1;
        __syncthreads();  // prior compute on `buf` done
        // store prefetched chunk (tf32-rounded)
#pragma unroll
        for (int j = 0; j < 4; ++j) {
            int kl = (aq + 4 * j) * 4;
            float4 v = pre[j];
            v.x = tf32r(v.x); v.y = tf32r(v.y); v.z = tf32r(v.z); v.w = tf32r(v.w);
            *(float4*)&a_s[buf][ar * 68 + kl] = v;
        }
        // prefetch next chunk (hide LDG latency behind compute)
        if (c + 1 < nchunks) {
            int k0c = (c + 1) * 64;
            const float* base;
            int ld, koff;
            if (k0c < IN_DIM) { base = xrow;  ld = IN_DIM; koff = k0c; }
            else              { base = hprev; ld = HID;    koff = k0c - IN_DIM; }
#pragma unroll
            for (int j = 0; j < 4; ++j) {
                int kg = koff + (aq + 4 * j) * 4;
                pre[j] = *(const float4*)(base + (size_t)ar * ld + kg);
            }
        }
        __syncthreads();  // buf filled
        const float* A = a_s[buf];
#pragma unroll
        for (int kk = 0; kk < 8; ++kk) {
            int ks = kk * 8;
            float a0 = A[(mb + gid) * 68 + ks + ktid];
            float a1 = A[(mb + gid + 8) * 68 + ks + ktid];
            float a2 = A[(mb + gid) * 68 + ks + ktid + 4];
            float a3 = A[(mb + gid + 8) * 68 + ks + ktid + 4];
            int gk = c * 8 + kk;
            float2 b0 = wp[gk * 128 + (nbase + gid) * 4 + ktid];
            float2 b1 = wp[gk * 128 + (nbase + 8 + gid) * 4 + ktid];
            mma_tf32(acc0, a0, a1, a2, a3, b0.x, b0.y);
            mma_tf32(acc1, a0, a1, a2, a3, b1.x, b1.y);
        }
    }

    // scatter accumulators to z_s
    {
        int cb0 = nbase + 2 * ktid;
        z_s[(mb + gid) * 33 + cb0]         = acc0[0];
        z_s[(mb + gid) * 33 + cb0 + 1]     = acc0[1];
        z_s[(mb + gid + 8) * 33 + cb0]     = acc0[2];
        z_s[(mb + gid + 8) * 33 + cb0 + 1] = acc0[3];
        int cb1 = nbase + 8 + 2 * ktid;
        z_s[(mb + gid) * 33 + cb1]         = acc1[0];
        z_s[(mb + gid) * 33 + cb1 + 1]     = acc1[1];
        z_s[(mb + gid + 8) * 33 + cb1]     = acc1[2];
        z_s[(mb + gid + 8) * 33 + cb1 + 1] = acc1[3];
    }
    __syncthreads();

    // gates + state update: 512 (b, cc) elements over 256 threads
    for (int i = tid; i < BATCH * HPC; i += 256) {
        int b  = i >> 3;
        int cc = i & 7;
        float zf = z_s[b * 33 + cc]      + bias_s[cc];
        float zi = z_s[b * 33 + 8 + cc]  + bias_s[8 + cc];
        float zg = z_s[b * 33 + 16 + cc] + bias_s[16 + cc];
        float zo = z_s[b * 33 + 24 + cc] + bias_s[24 + cc];
        float fg = 1.0f / (1.0f + __expf(-zf));
        float ig = 1.0f / (1.0f + __expf(-zi));
        float gg = tanhf(zg);
        float og = 1.0f / (1.0f + __expf(-zo));
        int hcol = cta * HPC + cc;
        float cold = (t == 0) ? 0.0f : g_c[b * HID + hcol];
        float cn = fg * cold + ig * gg;
        g_c[b * HID + hcol] = cn;
        out[(size_t)t * BATCH * HID + b * HID + hcol] = og * tanhf(cn);
    }
}

// hx = stacked[T-1], cx = g_c, appended after stacked
__global__ void finalize_kernel(float* out) {
    int i = blockIdx.x * blockDim.x + threadIdx.x;
    if (i < BATCH * HID) {
        size_t tail = (size_t)T_STEPS * BATCH * HID;
        out[tail + i] = out[(size_t)(T_STEPS - 1) * BATCH * HID + i];
        out[tail + BATCH * HID + i] = g_c[i];
    }
}

extern "C" void kernel_launch(void* const* d_in, const int* in_sizes, int n_in,
                              void* d_out, int out_size) {
    const float* x  = (const float*)d_in[0];
    const float* Wf = (const float*)d_in[1];
    const float* bf = (const float*)d_in[2];
    const float* Wi = (const float*)d_in[3];
    const float* bi = (const float*)d_in[4];
    const float* Wg = (const float*)d_in[5];
    const float* bg = (const float*)d_in[6];
    const float* Wo = (const float*)d_in[7];
    const float* bo = (const float*)d_in[8];
    float* out = (float*)d_out;

    int prep_threads = NCTA * CTA_W_F2;
    prep_kernel<<<(prep_threads + 255) / 256, 256>>>(Wf, bf, Wi, bi, Wg, bg, Wo, bo);

    for (int t = 0; t < T_STEPS; ++t)
        lstm_step_kernel<<<NCTA, 256>>>(x, out, t);

    finalize_kernel<<<(BATCH * HID + 255) / 256, 256>>>(out);
}

// round 4
// speedup vs baseline: 3.6233x; 3.6233x over previous
#include <cuda_runtime.h>
#include <cstdint>

#define TSTEPS  512
#define BATCH   64
#define IN_DIM  512
#define HID     1024
#define NCTA    128
#define COLS    32                 // z-cols per CTA = 4 gates x 8 hid cols
#define HPC     8
#define CTA_W_F2 24576             // 192 kpanels * (32 ncol * 4 ktid) float2
#define ZR_STRIDE 34
#define ZR_BUF   (64 * ZR_STRIDE)  // 2176 floats
#define W_SMEM_B 196608
#define SMEM_BYTES (W_SMEM_B + 4 * ZR_BUF * 4 + 128)   // 231552

// ---- static device scratch (no allocations) ----
__device__ float2   g_Wp[(size_t)NCTA * CTA_W_F2];   // packed tf32 W (~25MB)
__device__ float4   g_xp[(size_t)TSTEPS * 8192];     // x, fragment-permuted (~67MB)
__device__ float4   g_hp[2 * 16384];                 // h, fragment-permuted, dbl-buffered
__device__ float    g_bp[NCTA * COLS];               // packed bias
__device__ unsigned g_bar;                           // grid barrier counter

// ---------------- helpers ----------------
__device__ __forceinline__ float tf32r(float x) {
    unsigned r;
    asm("cvt.rna.tf32.f32 %0, %1;" : "=r"(r) : "f"(x));
    return __uint_as_float(r);
}
__device__ __forceinline__ void mma_tf32(float* c, float a0, float a1, float a2, float a3,
                                         float b0, float b1) {
    asm volatile(
        "mma.sync.aligned.m16n8k8.row.col.f32.tf32.tf32.f32 "
        "{%0,%1,%2,%3},{%4,%5,%6,%7},{%8,%9},{%0,%1,%2,%3};"
        : "+f"(c[0]), "+f"(c[1]), "+f"(c[2]), "+f"(c[3])
        : "r"(__float_as_uint(a0)), "r"(__float_as_uint(a1)),
          "r"(__float_as_uint(a2)), "r"(__float_as_uint(a3)),
          "r"(__float_as_uint(b0)), "r"(__float_as_uint(b1)));
}
__device__ __forceinline__ float4 ldcg4(const float4* p) {
    float4 v;
    asm volatile("ld.global.cg.v4.f32 {%0,%1,%2,%3}, [%4];"
                 : "=f"(v.x), "=f"(v.y), "=f"(v.z), "=f"(v.w) : "l"(p));
    return v;
}
__device__ __forceinline__ void load_panel(const float4* xb, const float4* hb,
                                           int p, int lane, float4* f) {
    const float4* b = (p < 64) ? (xb + (size_t)p * 128) : (hb + (size_t)(p - 64) * 128);
    b += lane;
    f[0] = ldcg4(b);
    f[1] = ldcg4(b + 32);
    f[2] = ldcg4(b + 64);
    f[3] = ldcg4(b + 96);
}
__device__ __forceinline__ void store_acc(float* zr, const float (&acc)[4][4][4],
                                          int gid, int ktid) {
#pragma unroll
    for (int mt = 0; mt < 4; ++mt)
#pragma unroll
        for (int n = 0; n < 4; ++n) {
            int r = mt * 16 + gid, cb = n * 8 + 2 * ktid;
            *(float2*)(zr + r * ZR_STRIDE + cb)       = make_float2(acc[mt][n][0], acc[mt][n][1]);
            *(float2*)(zr + (r + 8) * ZR_STRIDE + cb) = make_float2(acc[mt][n][2], acc[mt][n][3]);
        }
}
__device__ __forceinline__ void load_add(const float* zr, float (&acc)[4][4][4],
                                         int gid, int ktid) {
#pragma unroll
    for (int mt = 0; mt < 4; ++mt)
#pragma unroll
        for (int n = 0; n < 4; ++n) {
            int r = mt * 16 + gid, cb = n * 8 + 2 * ktid;
            float2 v0 = *(const float2*)(zr + r * ZR_STRIDE + cb);
            float2 v1 = *(const float2*)(zr + (r + 8) * ZR_STRIDE + cb);
            acc[mt][n][0] += v0.x; acc[mt][n][1] += v0.y;
            acc[mt][n][2] += v1.x; acc[mt][n][3] += v1.y;
        }
}

// ---------------- prep kernels ----------------
// Pack W into per-CTA mma-B-fragment order (tf32-rounded) + bias. (R1-proven.)
__global__ void prep_w(const float* __restrict__ Wf, const float* __restrict__ bf,
                       const float* __restrict__ Wi, const float* __restrict__ bi,
                       const float* __restrict__ Wg, const float* __restrict__ bg,
                       const float* __restrict__ Wo, const float* __restrict__ bo) {
    int idx = blockIdx.x * blockDim.x + threadIdx.x;
    if (idx < NCTA * COLS) {
        int cta = idx / COLS, ncol = idx % COLS;
        int gate = ncol >> 3, cc = ncol & 7;
        const float* bsrc = gate == 0 ? bf : gate == 1 ? bi : gate == 2 ? bg : bo;
        g_bp[idx] = bsrc[cta * HPC + cc];
    }
    if (idx >= NCTA * CTA_W_F2) return;
    int cta  = idx / CTA_W_F2;
    int rem  = idx % CTA_W_F2;
    int gk   = rem >> 7;
    int r2   = rem & 127;
    int ncol = r2 >> 2;
    int ktid = r2 & 3;
    int gate = ncol >> 3, cc = ncol & 7;
    int col  = cta * HPC + cc;
    int k0   = gk * 8;
    const float* Wsrc = gate == 0 ? Wf : gate == 1 ? Wi : gate == 2 ? Wg : Wo;
    float v0 = Wsrc[(size_t)(k0 + ktid) * HID + col];
    float v1 = Wsrc[(size_t)(k0 + ktid + 4) * HID + col];
    g_Wp[idx] = make_float2(tf32r(v0), tf32r(v1));
}

// Permute x into fragment-order float4 slots, tf32-rounded.
// Block handles (t, kg, mt): 16 batch rows x 128 k. Grid = 512*4*4 = 8192.
__global__ void prep_xp(const float* __restrict__ x) {
    __shared__ float tile[16 * 132];
    int bid = blockIdx.x;
    int mt = bid & 3, kg = (bid >> 2) & 3, t = bid >> 4;
    const float* src = x + (size_t)t * BATCH * IN_DIM + (size_t)(mt * 16) * IN_DIM + kg * 128;
    for (int i = threadIdx.x; i < 16 * 32; i += 256) {
        int r = i >> 5, c4 = (i & 31) * 4;
        float4 v = *(const float4*)(src + (size_t)r * IN_DIM + c4);
        tile[r * 132 + c4]     = v.x;
        tile[r * 132 + c4 + 1] = v.y;
        tile[r * 132 + c4 + 2] = v.z;
        tile[r * 132 + c4 + 3] = v.w;
    }
    __syncthreads();
    for (int o = threadIdx.x; o < 512; o += 256) {
        int pl = o >> 5, l = o & 31;
        int gid = l >> 2, kt = l & 3;
        int k0 = pl * 8;
        float4 v;
        v.x = tf32r(tile[gid * 132 + k0 + kt]);
        v.y = tf32r(tile[(gid + 8) * 132 + k0 + kt]);
        v.z = tf32r(tile[gid * 132 + k0 + kt + 4]);
        v.w = tf32r(tile[(gid + 8) * 132 + k0 + kt + 4]);
        g_xp[(size_t)(t * 64 + kg * 16 + pl) * 128 + mt * 32 + l] = v;
    }
}

__global__ void init_k() {
    int i = blockIdx.x * blockDim.x + threadIdx.x;
    float* h = (float*)g_hp;
    if (i < 2 * 65536) h[i] = 0.0f;
    if (i == 0) g_bar = 0u;
}

// ---------------- persistent LSTM kernel ----------------
__global__ void __launch_bounds__(256, 1) lstm_persist(float* __restrict__ out) {
    extern __shared__ char smem[];
    float2* Ws     = (float2*)smem;                       // 196608 B
    float*  zr     = (float*)(smem + W_SMEM_B);           // 4 * ZR_BUF floats
    float*  bias_s = (float*)(smem + W_SMEM_B + 4 * ZR_BUF * 4);

    const int tid = threadIdx.x, w = tid >> 5, lane = tid & 31;
    const int gid = lane >> 2, ktid = lane & 3;
    const int cta = blockIdx.x;

    {   // one-time W slice copy to smem (fragment order preserved)
        const float4* src = (const float4*)(g_Wp + (size_t)cta * CTA_W_F2);
        float4* dst = (float4*)Ws;
        for (int i = tid; i < 12288; i += 256) dst[i] = src[i];
    }
    if (tid < COLS) bias_s[tid] = g_bp[cta * COLS + tid];
    __syncthreads();

    float creg0 = 0.0f, creg1 = 0.0f;      // cell state in registers
    const int p0 = w * 24;                 // this warp's k-panels [p0, p0+24)

    for (int t = 0; t < TSTEPS; ++t) {
        if (t) {  // grid barrier: h_{t-1} published by all CTAs
            __syncthreads();
            if (tid == 0) {
                __threadfence();
                atomicAdd(&g_bar, 1u);
                unsigned v, tgt = (unsigned)NCTA * (unsigned)t;
                do {
                    asm volatile("ld.acquire.gpu.global.u32 %0, [%1];"
                                 : "=r"(v) : "l"(&g_bar) : "memory");
                } while (v < tgt);
            }
            __syncthreads();
        }

        float acc[4][4][4];
#pragma unroll
        for (int a = 0; a < 4; ++a)
#pragma unroll
            for (int b = 0; b < 4; ++b)
#pragma unroll
                for (int c = 0; c < 4; ++c) acc[a][b][c] = 0.0f;

        const float4* xb = g_xp + (size_t)t * 8192;
        const float4* hb = g_hp + (size_t)((t - 1) & 1) * 16384;

        float4 fr[3][4];
        load_panel(xb, hb, p0, lane, fr[0]);
        load_panel(xb, hb, p0 + 1, lane, fr[1]);
#pragma unroll
        for (int i = 0; i < 24; ++i) {
            if (i < 22) load_panel(xb, hb, p0 + i + 2, lane, fr[(i + 2) % 3]);
            float2 bq[4];
            const float2* wrow = Ws + (p0 + i) * 128 + gid * 4 + ktid;
#pragma unroll
            for (int n = 0; n < 4; ++n) bq[n] = wrow[n * 32];
            float4* f = fr[i % 3];
#pragma unroll
            for (int mt = 0; mt < 4; ++mt)
#pragma unroll
                for (int n = 0; n < 4; ++n)
                    mma_tf32(acc[mt][n], f[mt].x, f[mt].y, f[mt].z, f[mt].w,
                             bq[n].x, bq[n].y);
        }

        // ---- 3-round k-partial reduction (8 warps -> 1) ----
        if (w >= 4) store_acc(zr + (w - 4) * ZR_BUF, acc, gid, ktid);
        __syncthreads();
        if (w < 4)  load_add(zr + w * ZR_BUF, acc, gid, ktid);
        __syncthreads();
        if (w == 2) store_acc(zr, acc, gid, ktid);
        if (w == 3) store_acc(zr + ZR_BUF, acc, gid, ktid);
        __syncthreads();
        if (w < 2)  load_add(zr + w * ZR_BUF, acc, gid, ktid);
        __syncthreads();
        if (w == 1) store_acc(zr + ZR_BUF, acc, gid, ktid);
        __syncthreads();
        if (w == 0) { load_add(zr + ZR_BUF, acc, gid, ktid); store_acc(zr, acc, gid, ktid); }
        __syncthreads();

        // ---- fused gate epilogue: 512 (b, cc) elements over 256 threads ----
#pragma unroll
        for (int half = 0; half < 2; ++half) {
            int e  = tid + half * 256;
            int b  = e >> 3, cx = e & 7;
            float zf = zr[b * ZR_STRIDE + cx]      + bias_s[cx];
            float zi = zr[b * ZR_STRIDE + 8 + cx]  + bias_s[8 + cx];
            float zg = zr[b * ZR_STRIDE + 16 + cx] + bias_s[16 + cx];
            float zo = zr[b * ZR_STRIDE + 24 + cx] + bias_s[24 + cx];
            float fg = 1.0f / (1.0f + __expf(-zf));
            float ig = 1.0f / (1.0f + __expf(-zi));
            float gg = tanhf(zg);
            float og = 1.0f / (1.0f + __expf(-zo));
            float cold = half ? creg1 : creg0;
            float cn = fg * cold + ig * gg;
            if (half) creg1 = cn; else creg0 = cn;
            float h = og * tanhf(cn);
            int hcol = cta * HPC + cx;
            out[(size_t)t * (BATCH * HID) + b * HID + hcol] = h;
            // fragment-permuted tf32 h for next step's A operand
            int p   = hcol >> 3, j = hcol & 7;
            int mt  = b >> 4, g8 = b & 7, hh = (b >> 3) & 1;
            int kt2 = j & 3, comp = ((j >> 2) << 1) | hh;
            ((float*)g_hp)[((size_t)(t & 1) * 16384 + (size_t)(p * 4 + mt) * 32 +
                            g8 * 4 + kt2) * 4 + comp] = tf32r(h);
            if (t == TSTEPS - 1) {
                size_t tail = (size_t)TSTEPS * BATCH * HID;
                out[tail + b * HID + hcol] = h;
                out[tail + BATCH * HID + b * HID + hcol] = cn;
            }
        }
        __syncthreads();   // zr reuse safety for next step
    }
}

// ---------------- host ----------------
extern "C" void kernel_launch(void* const* d_in, const int* in_sizes, int n_in,
                              void* d_out, int out_size) {
    const float* x  = (const float*)d_in[0];
    const float* Wf = (const float*)d_in[1];
    const float* bf = (const float*)d_in[2];
    const float* Wi = (const float*)d_in[3];
    const float* bi = (const float*)d_in[4];
    const float* Wg = (const float*)d_in[5];
    const float* bg = (const float*)d_in[6];
    const float* Wo = (const float*)d_in[7];
    const float* bo = (const float*)d_in[8];
    float* out = (float*)d_out;

    static int attr_done = 0;
    if (!attr_done) {
        cudaFuncSetAttribute(lstm_persist, cudaFuncAttributeMaxDynamicSharedMemorySize,
                             SMEM_BYTES);
        attr_done = 1;
    }

    init_k<<<512, 256>>>();
    prep_w<<<(NCTA * CTA_W_F2 + 255) / 256, 256>>>(Wf, bf, Wi, bi, Wg, bg, Wo, bo);
    prep_xp<<<8192, 256>>>(x);
    lstm_persist<<<NCTA, 256, SMEM_BYTES>>>(out);
}